// round 9
// baseline (speedup 1.0000x reference)
#include <cuda_runtime.h>
#include <math.h>
#include <stdint.h>

#define B 16384
#define C 100
#define D 512
#define Z 128
#define BETA 50000000.0
#define EPSF 1e-8f

#define GRID        148
#define THREADS     384          // 12 warps
#define RPS         2            // rows per stage
#define NSTAGE      (B / RPS)    // 8192
#define NBUF        4

// stage layout in floats
#define OFF_TUBE(pair, al) (((pair) * 2 + (al)) * (RPS * D))   // 8 x 1024 floats
#define OFF_MU   8192
#define OFF_LV   8448
#define OFF_F    8704
#define OFF_LB   8904
#define STAGE_FLOATS 9104
#define STAGE_BYTES  (STAGE_FLOATS * 4)          // 36416
#define SMEM_BYTES   (NBUF * STAGE_BYTES + 32)   // + 4 mbarriers

__device__ double g_acc[3] = {0.0, 0.0, 0.0};
__device__ unsigned g_count = 0u;

__device__ __forceinline__ uint32_t smem_u32(const void* p) {
    uint32_t a;
    asm("{ .reg .u64 t; cvta.to.shared.u64 t, %1; cvt.u32.u64 %0, t; }" : "=r"(a) : "l"(p));
    return a;
}

__device__ __forceinline__ void bulk_cp(uint32_t dst, const void* src, uint32_t bytes, uint32_t bar) {
    asm volatile("cp.async.bulk.shared::cluster.global.mbarrier::complete_tx::bytes [%0], [%1], %2, [%3];"
                 :: "r"(dst), "l"(src), "r"(bytes), "r"(bar) : "memory");
}

__device__ __forceinline__ void mbar_wait(uint32_t bar, uint32_t parity) {
    uint32_t done;
    asm volatile("{ .reg .pred p; mbarrier.try_wait.parity.acquire.cta.shared::cta.b64 p, [%1], %2; selp.b32 %0, 1, 0, p; }"
                 : "=r"(done) : "r"(bar), "r"(parity) : "memory");
    if (!done) {
        asm volatile("{ .reg .pred P1; WL%=: mbarrier.try_wait.parity.acquire.cta.shared::cta.b64 P1, [%0], %1, 0x989680; @P1 bra.uni WD%=; bra.uni WL%=; WD%=: }"
                     :: "r"(bar), "r"(parity) : "memory");
    }
}

__device__ __forceinline__ float warp_sum(float v) {
#pragma unroll
    for (int o = 16; o; o >>= 1) v += __shfl_xor_sync(0xffffffffu, v, o);
    return v;
}

__device__ __forceinline__ float tube_scalar(float dot, float pp, float gg) {
    float p = sqrtf(pp);
    float g = sqrtf(gg);
    float denom = p * g;
    float cosine = (denom == 0.f) ? 0.f : (dot / denom);
    float s_s = 1.f - cosine * cosine;
    float sine = (s_s < 0.f) ? 0.f : sqrtf((s_s <= 0.f) ? EPSF : s_s);
    float gd = (g == 0.f) ? (g + EPSF) : g;
    float pc = p * cosine;
    float r_all = pc / gd;
    float ps = p * sine;
    float ds;
    if (r_all >= 1.f)       ds = 0.5f * (ps + fabsf(g - pc));
    else if (r_all >= 0.f)  ds = ps + fabsf(g - pc);
    else                    ds = 1.5f * fabsf(pc - g - ps);
    return -__logf(tanhf(1.f / ds));   // ds==0 -> inf -> tanh=1 -> 0, matches jax
}

extern __shared__ float smem[];

__device__ __forceinline__ void issue_stage(
    int s, uint32_t dst, uint32_t bar,
    const float* const* atts, const float* const* labs,
    const float* mu, const float* lv, const float* fusion, const float* labels)
{
    asm volatile("mbarrier.arrive.expect_tx.shared.b64 _, [%0], %1;"
                 :: "r"(bar), "r"((uint32_t)STAGE_BYTES) : "memory");
#pragma unroll
    for (int j = 0; j < 4; j++) {
        bulk_cp(dst + OFF_TUBE(j, 0) * 4, atts[j] + (long)s * (RPS * D), RPS * D * 4, bar);
        bulk_cp(dst + OFF_TUBE(j, 1) * 4, labs[j] + (long)s * (RPS * D), RPS * D * 4, bar);
    }
    bulk_cp(dst + OFF_MU * 4, mu     + (long)s * (RPS * Z), RPS * Z * 4, bar);
    bulk_cp(dst + OFF_LV * 4, lv     + (long)s * (RPS * Z), RPS * Z * 4, bar);
    bulk_cp(dst + OFF_F  * 4, fusion + (long)s * (RPS * C), RPS * C * 4, bar);
    bulk_cp(dst + OFF_LB * 4, labels + (long)s * (RPS * C), RPS * C * 4, bar);
}

__global__ void __launch_bounds__(THREADS, 1)
loss_kernel(const float* __restrict__ fusion,
            const float* __restrict__ comple,
            const float* __restrict__ labels,
            const float* __restrict__ lab_enc,
            const float* __restrict__ xA,  const float* __restrict__ xAr,
            const float* __restrict__ xB,  const float* __restrict__ xBr,
            const float* __restrict__ xC,  const float* __restrict__ xCr,
            const float* __restrict__ mu,  const float* __restrict__ lv,
            float* __restrict__ out)
{
    const int tid  = threadIdx.x;
    const int warp = tid >> 5;
    const int lane = tid & 31;
    const int bid  = blockIdx.x;

    const float* atts[4] = { xAr, xBr, xCr, comple };
    const float* labs[4] = { xA,  xB,  xC,  lab_enc };

    const uint32_t smem_base = smem_u32(smem);
    const uint32_t bar_base  = smem_base + NBUF * STAGE_BYTES;

    if (tid == 0) {
#pragma unroll
        for (int k = 0; k < NBUF; k++)
            asm volatile("mbarrier.init.shared.b64 [%0], 1;" :: "r"(bar_base + k * 8) : "memory");
        asm volatile("fence.proxy.async.shared::cta;" ::: "memory");
    }
    __syncthreads();

    const int nIter = (NSTAGE - bid + GRID - 1) / GRID;   // 55 or 56

    // prologue: fill all NBUF buffers
    if (tid == 0) {
#pragma unroll
        for (int k = 0; k < NBUF; k++) {
            const int s = bid + k * GRID;
            if (k < nIter)
                issue_stage(s, smem_base + k * STAGE_BYTES, bar_base + k * 8,
                            atts, labs, mu, lv, fusion, labels);
        }
    }

    float tube = 0.f, ce = 0.f, kl = 0.f;

    for (int it = 0; it < nIter; it++) {
        const int buf = it & (NBUF - 1);
        const uint32_t parity = (it / NBUF) & 1;
        mbar_wait(bar_base + buf * 8, parity);

        const float* bufp = smem + buf * STAGE_FLOATS;

        // 12 tasks over 12 warps: 0-7 tube (row=warp>>2, pair=warp&3), 8-9 KL, 10-11 CE
        if (warp < 8) {
            const int row = warp >> 2, pair = warp & 3;
            const float4* a4 = (const float4*)(bufp + OFF_TUBE(pair, 0) + row * D);
            const float4* g4 = (const float4*)(bufp + OFF_TUBE(pair, 1) + row * D);
            float dot = 0.f, pp = 0.f, gg = 0.f;
#pragma unroll
            for (int i = 0; i < 4; i++) {
                float4 a = a4[lane + 32 * i];
                float4 g = g4[lane + 32 * i];
                dot += a.x * g.x + a.y * g.y + a.z * g.z + a.w * g.w;
                pp  += a.x * a.x + a.y * a.y + a.z * a.z + a.w * a.w;
                gg  += g.x * g.x + g.y * g.y + g.z * g.z + g.w * g.w;
            }
            dot = warp_sum(dot);
            pp  = warp_sum(pp);
            gg  = warp_sum(gg);
            tube += tube_scalar(dot, pp, gg);
        } else if (warp < 10) {
            const int row = warp - 8;
            float4 m = ((const float4*)(bufp + OFF_MU + row * Z))[lane];
            float4 l = ((const float4*)(bufp + OFF_LV + row * Z))[lane];
            float k = (1.f + l.x - m.x * m.x - __expf(l.x))
                    + (1.f + l.y - m.y * m.y - __expf(l.y))
                    + (1.f + l.z - m.z * m.z - __expf(l.z))
                    + (1.f + l.w - m.w * m.w - __expf(l.w));
            kl += warp_sum(k);
        } else {
            const int row = warp - 10;
            const float* f  = bufp + OFF_F  + row * C;
            const float* lb = bufp + OFF_LB + row * C;
            float fmax = -INFINITY, lmax = -INFINITY;
            int lidx = 0x7fffffff;
#pragma unroll
            for (int q = 0; q < 4; q++) {
                int i = lane + 32 * q;
                if (i < C) {
                    float fv  = f[i];
                    float lvv = lb[i];
                    fmax = fmaxf(fmax, fv);
                    if (lvv > lmax || (lvv == lmax && i < lidx)) { lmax = lvv; lidx = i; }
                }
            }
#pragma unroll
            for (int o = 16; o; o >>= 1) {
                fmax = fmaxf(fmax, __shfl_xor_sync(0xffffffffu, fmax, o));
                float ol = __shfl_xor_sync(0xffffffffu, lmax, o);
                int   oi = __shfl_xor_sync(0xffffffffu, lidx, o);
                if (ol > lmax || (ol == lmax && oi < lidx)) { lmax = ol; lidx = oi; }
            }
            float se = 0.f;
#pragma unroll
            for (int q = 0; q < 4; q++) {
                int i = lane + 32 * q;
                if (i < C) se += __expf(f[i] - fmax);
            }
            se = warp_sum(se);
            ce += -(f[lidx] - fmax - __logf(se));
        }

        __syncthreads();   // all warps done reading this buffer

        // refill this buffer for stage it+NBUF
        if (tid == 0) {
            const int nx = it + NBUF;
            if (nx < nIter) {
                asm volatile("fence.proxy.async.shared::cta;" ::: "memory");
                issue_stage(bid + nx * GRID, smem_base + buf * STAGE_BYTES, bar_base + buf * 8,
                            atts, labs, mu, lv, fusion, labels);
            }
        }
    }

    // ---- block reduce + last-block finalize ----
    __shared__ float sT[12], sC[12], sK[12];
    if (lane == 0) { sT[warp] = tube; sC[warp] = ce; sK[warp] = kl; }
    __syncthreads();
    if (tid == 0) {
        float t = 0.f, c = 0.f, k = 0.f;
#pragma unroll
        for (int i = 0; i < 12; i++) { t += sT[i]; c += sC[i]; k += sK[i]; }
        atomicAdd(&g_acc[0], (double)t);
        atomicAdd(&g_acc[1], (double)c);
        atomicAdd(&g_acc[2], (double)k);
        __threadfence();
        unsigned prev = atomicAdd(&g_count, 1u);
        if (prev == gridDim.x - 1) {
            __threadfence();
            double tubeS = g_acc[0] / (double)B;                         // ALPHA = 1
            double ceS   = g_acc[1] / (double)B;
            double klS   = -0.5 * BETA * (g_acc[2] / ((double)B * (double)Z));
            out[0] = (float)(tubeS + ceS + klS);
            g_acc[0] = 0.0; g_acc[1] = 0.0; g_acc[2] = 0.0;
            g_count = 0u;
            __threadfence();
        }
    }
}

extern "C" void kernel_launch(void* const* d_in, const int* in_sizes, int n_in,
                              void* d_out, int out_size) {
    const float* fusion  = (const float*)d_in[0];
    const float* comple  = (const float*)d_in[1];
    const float* labels  = (const float*)d_in[2];
    const float* lab_enc = (const float*)d_in[3];
    const float* xA      = (const float*)d_in[4];
    const float* xAr     = (const float*)d_in[5];
    const float* xB      = (const float*)d_in[6];
    const float* xBr     = (const float*)d_in[7];
    const float* xC      = (const float*)d_in[8];
    const float* xCr     = (const float*)d_in[9];
    const float* mu      = (const float*)d_in[10];
    const float* lv      = (const float*)d_in[11];
    float* out = (float*)d_out;

    static int configured = 0;
    if (!configured) {
        cudaFuncSetAttribute(loss_kernel, cudaFuncAttributeMaxDynamicSharedMemorySize, SMEM_BYTES);
        configured = 1;
    }
    loss_kernel<<<GRID, THREADS, SMEM_BYTES>>>(fusion, comple, labels, lab_enc,
                                               xA, xAr, xB, xBr, xC, xCr, mu, lv, out);
}

// round 10
// speedup vs baseline: 1.1796x; 1.1796x over previous
#include <cuda_runtime.h>
#include <math.h>
#include <stdint.h>

#define B 16384
#define C 100
#define D 512
#define Z 128
#define BETA 50000000.0
#define EPSF 1e-8f

#define GRID        148
#define THREADS     384          // 12 warps
#define RPS         4            // rows per stage
#define NSTAGE      (B / RPS)    // 4096
#define NBUF        3

// stage layout in floats
#define OFF_TUBE(pair, al) (((pair) * 2 + (al)) * (RPS * D))   // 8 x 2048 floats
#define OFF_MU   16384
#define OFF_LV   16896
#define OFF_F    17408
#define OFF_LB   17808
#define STAGE_FLOATS 18208
#define STAGE_BYTES  (STAGE_FLOATS * 4)          // 72832
#define SMEM_BYTES   (NBUF * STAGE_BYTES + 32)   // 218528 incl. mbarriers

__device__ double g_acc[3] = {0.0, 0.0, 0.0};
__device__ unsigned g_count = 0u;

__device__ __forceinline__ uint32_t smem_u32(const void* p) {
    uint32_t a;
    asm("{ .reg .u64 t; cvta.to.shared.u64 t, %1; cvt.u32.u64 %0, t; }" : "=r"(a) : "l"(p));
    return a;
}

__device__ __forceinline__ void bulk_cp(uint32_t dst, const void* src, uint32_t bytes, uint32_t bar) {
    asm volatile("cp.async.bulk.shared::cluster.global.mbarrier::complete_tx::bytes [%0], [%1], %2, [%3];"
                 :: "r"(dst), "l"(src), "r"(bytes), "r"(bar) : "memory");
}

__device__ __forceinline__ void mbar_wait(uint32_t bar, uint32_t parity) {
    uint32_t done;
    asm volatile("{ .reg .pred p; mbarrier.try_wait.parity.acquire.cta.shared::cta.b64 p, [%1], %2; selp.b32 %0, 1, 0, p; }"
                 : "=r"(done) : "r"(bar), "r"(parity) : "memory");
    if (!done) {
        asm volatile("{ .reg .pred P1; WL%=: mbarrier.try_wait.parity.acquire.cta.shared::cta.b64 P1, [%0], %1, 0x989680; @P1 bra.uni WD%=; bra.uni WL%=; WD%=: }"
                     :: "r"(bar), "r"(parity) : "memory");
    }
}

__device__ __forceinline__ float warp_sum(float v) {
#pragma unroll
    for (int o = 16; o; o >>= 1) v += __shfl_xor_sync(0xffffffffu, v, o);
    return v;
}

__device__ __forceinline__ float tube_scalar(float dot, float pp, float gg) {
    float p = sqrtf(pp);
    float g = sqrtf(gg);
    float denom = p * g;
    float cosine = (denom == 0.f) ? 0.f : (dot / denom);
    float s_s = 1.f - cosine * cosine;
    float sine = (s_s < 0.f) ? 0.f : sqrtf((s_s <= 0.f) ? EPSF : s_s);
    float gd = (g == 0.f) ? (g + EPSF) : g;
    float pc = p * cosine;
    float r_all = pc / gd;
    float ps = p * sine;
    float ds;
    if (r_all >= 1.f)       ds = 0.5f * (ps + fabsf(g - pc));
    else if (r_all >= 0.f)  ds = ps + fabsf(g - pc);
    else                    ds = 1.5f * fabsf(pc - g - ps);
    return -__logf(tanhf(1.f / ds));   // ds==0 -> inf -> tanh=1 -> 0, matches jax
}

extern __shared__ float smem[];

__device__ __forceinline__ void issue_stage(
    int s, uint32_t dst, uint32_t bar,
    const float* const* atts, const float* const* labs,
    const float* mu, const float* lv, const float* fusion, const float* labels)
{
    asm volatile("mbarrier.arrive.expect_tx.shared.b64 _, [%0], %1;"
                 :: "r"(bar), "r"((uint32_t)STAGE_BYTES) : "memory");
#pragma unroll
    for (int j = 0; j < 4; j++) {
        bulk_cp(dst + OFF_TUBE(j, 0) * 4, atts[j] + (long)s * (RPS * D), RPS * D * 4, bar);
        bulk_cp(dst + OFF_TUBE(j, 1) * 4, labs[j] + (long)s * (RPS * D), RPS * D * 4, bar);
    }
    bulk_cp(dst + OFF_MU * 4, mu     + (long)s * (RPS * Z), RPS * Z * 4, bar);
    bulk_cp(dst + OFF_LV * 4, lv     + (long)s * (RPS * Z), RPS * Z * 4, bar);
    bulk_cp(dst + OFF_F  * 4, fusion + (long)s * (RPS * C), RPS * C * 4, bar);
    bulk_cp(dst + OFF_LB * 4, labels + (long)s * (RPS * C), RPS * C * 4, bar);
}

__global__ void __launch_bounds__(THREADS, 1)
loss_kernel(const float* __restrict__ fusion,
            const float* __restrict__ comple,
            const float* __restrict__ labels,
            const float* __restrict__ lab_enc,
            const float* __restrict__ xA,  const float* __restrict__ xAr,
            const float* __restrict__ xB,  const float* __restrict__ xBr,
            const float* __restrict__ xC,  const float* __restrict__ xCr,
            const float* __restrict__ mu,  const float* __restrict__ lv,
            float* __restrict__ out)
{
    const int tid  = threadIdx.x;
    const int warp = tid >> 5;
    const int lane = tid & 31;
    const int bid  = blockIdx.x;

    const float* atts[4] = { xAr, xBr, xCr, comple };
    const float* labs[4] = { xA,  xB,  xC,  lab_enc };

    const uint32_t smem_base = smem_u32(smem);
    const uint32_t bar_base  = smem_base + NBUF * STAGE_BYTES;

    if (tid == 0) {
#pragma unroll
        for (int k = 0; k < NBUF; k++)
            asm volatile("mbarrier.init.shared.b64 [%0], 1;" :: "r"(bar_base + k * 8) : "memory");
        asm volatile("fence.proxy.async.shared::cta;" ::: "memory");
    }
    __syncthreads();

    const int nIter = (NSTAGE - bid + GRID - 1) / GRID;   // 27 or 28, >= NBUF

    // prologue: fill all NBUF buffers
    if (tid == 0) {
#pragma unroll
        for (int k = 0; k < NBUF; k++) {
            issue_stage(bid + k * GRID, smem_base + k * STAGE_BYTES, bar_base + k * 8,
                        atts, labs, mu, lv, fusion, labels);
        }
    }

    float tube = 0.f, ce = 0.f, kl = 0.f;
    int buf = 0;
    unsigned parity = 0;

    for (int it = 0; it < nIter; it++) {
        mbar_wait(bar_base + buf * 8, parity);

        const float* bufp = smem + buf * STAGE_FLOATS;

        // 24 tasks over 12 warps: 0-15 tube (row=t>>2, pair=t&3), 16-19 KL, 20-23 CE
#pragma unroll
        for (int tt = 0; tt < 2; tt++) {
            const int t = warp * 2 + tt;
            if (t < 16) {
                const int row = t >> 2, pair = t & 3;
                const float4* a4 = (const float4*)(bufp + OFF_TUBE(pair, 0) + row * D);
                const float4* g4 = (const float4*)(bufp + OFF_TUBE(pair, 1) + row * D);
                float dot = 0.f, pp = 0.f, gg = 0.f;
#pragma unroll
                for (int i = 0; i < 4; i++) {
                    float4 a = a4[lane + 32 * i];
                    float4 g = g4[lane + 32 * i];
                    dot += a.x * g.x + a.y * g.y + a.z * g.z + a.w * g.w;
                    pp  += a.x * a.x + a.y * a.y + a.z * a.z + a.w * a.w;
                    gg  += g.x * g.x + g.y * g.y + g.z * g.z + g.w * g.w;
                }
                dot = warp_sum(dot);
                pp  = warp_sum(pp);
                gg  = warp_sum(gg);
                tube += tube_scalar(dot, pp, gg);
            } else if (t < 20) {
                const int row = t - 16;
                float4 m = ((const float4*)(bufp + OFF_MU + row * Z))[lane];
                float4 l = ((const float4*)(bufp + OFF_LV + row * Z))[lane];
                float k = (1.f + l.x - m.x * m.x - __expf(l.x))
                        + (1.f + l.y - m.y * m.y - __expf(l.y))
                        + (1.f + l.z - m.z * m.z - __expf(l.z))
                        + (1.f + l.w - m.w * m.w - __expf(l.w));
                kl += warp_sum(k);
            } else {
                const int row = t - 20;
                const float* f  = bufp + OFF_F  + row * C;
                const float* lb = bufp + OFF_LB + row * C;
                float fmax = -INFINITY, lmax = -INFINITY;
                int lidx = 0x7fffffff;
#pragma unroll
                for (int q = 0; q < 4; q++) {
                    int i = lane + 32 * q;
                    if (i < C) {
                        float fv  = f[i];
                        float lvv = lb[i];
                        fmax = fmaxf(fmax, fv);
                        if (lvv > lmax || (lvv == lmax && i < lidx)) { lmax = lvv; lidx = i; }
                    }
                }
#pragma unroll
                for (int o = 16; o; o >>= 1) {
                    fmax = fmaxf(fmax, __shfl_xor_sync(0xffffffffu, fmax, o));
                    float ol = __shfl_xor_sync(0xffffffffu, lmax, o);
                    int   oi = __shfl_xor_sync(0xffffffffu, lidx, o);
                    if (ol > lmax || (ol == lmax && oi < lidx)) { lmax = ol; lidx = oi; }
                }
                float se = 0.f;
#pragma unroll
                for (int q = 0; q < 4; q++) {
                    int i = lane + 32 * q;
                    if (i < C) se += __expf(f[i] - fmax);
                }
                se = warp_sum(se);
                ce += -(f[lidx] - fmax - __logf(se));
            }
        }

        __syncthreads();   // all warps done reading this buffer

        // refill this buffer for stage it+NBUF
        if (tid == 0) {
            const int nx = it + NBUF;
            if (nx < nIter) {
                asm volatile("fence.proxy.async.shared::cta;" ::: "memory");
                issue_stage(bid + nx * GRID, smem_base + buf * STAGE_BYTES, bar_base + buf * 8,
                            atts, labs, mu, lv, fusion, labels);
            }
        }

        if (++buf == NBUF) { buf = 0; parity ^= 1u; }
    }

    // ---- block reduce + last-block finalize ----
    __shared__ float sT[12], sC[12], sK[12];
    if (lane == 0) { sT[warp] = tube; sC[warp] = ce; sK[warp] = kl; }
    __syncthreads();
    if (tid == 0) {
        float t = 0.f, c = 0.f, k = 0.f;
#pragma unroll
        for (int i = 0; i < 12; i++) { t += sT[i]; c += sC[i]; k += sK[i]; }
        atomicAdd(&g_acc[0], (double)t);
        atomicAdd(&g_acc[1], (double)c);
        atomicAdd(&g_acc[2], (double)k);
        __threadfence();
        unsigned prev = atomicAdd(&g_count, 1u);
        if (prev == gridDim.x - 1) {
            __threadfence();
            double tubeS = g_acc[0] / (double)B;                         // ALPHA = 1
            double ceS   = g_acc[1] / (double)B;
            double klS   = -0.5 * BETA * (g_acc[2] / ((double)B * (double)Z));
            out[0] = (float)(tubeS + ceS + klS);
            g_acc[0] = 0.0; g_acc[1] = 0.0; g_acc[2] = 0.0;
            g_count = 0u;
            __threadfence();
        }
    }
}

extern "C" void kernel_launch(void* const* d_in, const int* in_sizes, int n_in,
                              void* d_out, int out_size) {
    const float* fusion  = (const float*)d_in[0];
    const float* comple  = (const float*)d_in[1];
    const float* labels  = (const float*)d_in[2];
    const float* lab_enc = (const float*)d_in[3];
    const float* xA      = (const float*)d_in[4];
    const float* xAr     = (const float*)d_in[5];
    const float* xB      = (const float*)d_in[6];
    const float* xBr     = (const float*)d_in[7];
    const float* xC      = (const float*)d_in[8];
    const float* xCr     = (const float*)d_in[9];
    const float* mu      = (const float*)d_in[10];
    const float* lv      = (const float*)d_in[11];
    float* out = (float*)d_out;

    static int configured = 0;
    if (!configured) {
        cudaFuncSetAttribute(loss_kernel, cudaFuncAttributeMaxDynamicSharedMemorySize, SMEM_BYTES);
        configured = 1;
    }
    loss_kernel<<<GRID, THREADS, SMEM_BYTES>>>(fusion, comple, labels, lab_enc,
                                               xA, xAr, xB, xBr, xC, xCr, mu, lv, out);
}

// round 11
// speedup vs baseline: 1.2437x; 1.0543x over previous
#include <cuda_runtime.h>
#include <math.h>
#include <stdint.h>

#define B 16384
#define C 100
#define D 512
#define Z 128
#define BETA 50000000.0
#define EPSF 1e-8f

#define GRID        148
#define THREADS     416          // 12 consumer warps + 1 producer warp
#define NCONS       12
#define RPS         4            // rows per stage
#define NSTAGE      (B / RPS)    // 4096
#define NBUF        3

// stage layout in floats
#define OFF_TUBE(pair, al) (((pair) * 2 + (al)) * (RPS * D))   // 8 x 2048 floats
#define OFF_MU   16384
#define OFF_LV   16896
#define OFF_F    17408
#define OFF_LB   17808
#define STAGE_FLOATS 18208
#define STAGE_BYTES  (STAGE_FLOATS * 4)          // 72832
// barriers: full[0..2] then empty[0..2]
#define SMEM_BYTES   (NBUF * STAGE_BYTES + 64)

__device__ double g_acc[3] = {0.0, 0.0, 0.0};
__device__ unsigned g_count = 0u;

__device__ __forceinline__ uint32_t smem_u32(const void* p) {
    uint32_t a;
    asm("{ .reg .u64 t; cvta.to.shared.u64 t, %1; cvt.u32.u64 %0, t; }" : "=r"(a) : "l"(p));
    return a;
}

__device__ __forceinline__ void bulk_cp(uint32_t dst, const void* src, uint32_t bytes, uint32_t bar) {
    asm volatile("cp.async.bulk.shared::cluster.global.mbarrier::complete_tx::bytes [%0], [%1], %2, [%3];"
                 :: "r"(dst), "l"(src), "r"(bytes), "r"(bar) : "memory");
}

__device__ __forceinline__ void mbar_wait(uint32_t bar, uint32_t parity) {
    uint32_t done;
    asm volatile("{ .reg .pred p; mbarrier.try_wait.parity.acquire.cta.shared::cta.b64 p, [%1], %2; selp.b32 %0, 1, 0, p; }"
                 : "=r"(done) : "r"(bar), "r"(parity) : "memory");
    if (!done) {
        asm volatile("{ .reg .pred P1; WL%=: mbarrier.try_wait.parity.acquire.cta.shared::cta.b64 P1, [%0], %1, 0x989680; @P1 bra.uni WD%=; bra.uni WL%=; WD%=: }"
                     :: "r"(bar), "r"(parity) : "memory");
    }
}

__device__ __forceinline__ void mbar_arrive(uint32_t bar) {
    asm volatile("mbarrier.arrive.release.cta.shared::cta.b64 _, [%0];" :: "r"(bar) : "memory");
}

__device__ __forceinline__ float warp_sum(float v) {
#pragma unroll
    for (int o = 16; o; o >>= 1) v += __shfl_xor_sync(0xffffffffu, v, o);
    return v;
}

__device__ __forceinline__ float tube_scalar(float dot, float pp, float gg) {
    float p = sqrtf(pp);
    float g = sqrtf(gg);
    float denom = p * g;
    float cosine = (denom == 0.f) ? 0.f : (dot / denom);
    float s_s = 1.f - cosine * cosine;
    float sine = (s_s < 0.f) ? 0.f : sqrtf((s_s <= 0.f) ? EPSF : s_s);
    float gd = (g == 0.f) ? (g + EPSF) : g;
    float pc = p * cosine;
    float r_all = pc / gd;
    float ps = p * sine;
    float ds;
    if (r_all >= 1.f)       ds = 0.5f * (ps + fabsf(g - pc));
    else if (r_all >= 0.f)  ds = ps + fabsf(g - pc);
    else                    ds = 1.5f * fabsf(pc - g - ps);
    return -__logf(tanhf(1.f / ds));   // ds==0 -> inf -> tanh=1 -> 0, matches jax
}

extern __shared__ float smem[];

__device__ __forceinline__ void issue_stage(
    int s, uint32_t dst, uint32_t bar,
    const float* const* atts, const float* const* labs,
    const float* mu, const float* lv, const float* fusion, const float* labels)
{
    asm volatile("mbarrier.arrive.expect_tx.shared.b64 _, [%0], %1;"
                 :: "r"(bar), "r"((uint32_t)STAGE_BYTES) : "memory");
#pragma unroll
    for (int j = 0; j < 4; j++) {
        bulk_cp(dst + OFF_TUBE(j, 0) * 4, atts[j] + (long)s * (RPS * D), RPS * D * 4, bar);
        bulk_cp(dst + OFF_TUBE(j, 1) * 4, labs[j] + (long)s * (RPS * D), RPS * D * 4, bar);
    }
    bulk_cp(dst + OFF_MU * 4, mu     + (long)s * (RPS * Z), RPS * Z * 4, bar);
    bulk_cp(dst + OFF_LV * 4, lv     + (long)s * (RPS * Z), RPS * Z * 4, bar);
    bulk_cp(dst + OFF_F  * 4, fusion + (long)s * (RPS * C), RPS * C * 4, bar);
    bulk_cp(dst + OFF_LB * 4, labels + (long)s * (RPS * C), RPS * C * 4, bar);
}

__global__ void __launch_bounds__(THREADS, 1)
loss_kernel(const float* __restrict__ fusion,
            const float* __restrict__ comple,
            const float* __restrict__ labels,
            const float* __restrict__ lab_enc,
            const float* __restrict__ xA,  const float* __restrict__ xAr,
            const float* __restrict__ xB,  const float* __restrict__ xBr,
            const float* __restrict__ xC,  const float* __restrict__ xCr,
            const float* __restrict__ mu,  const float* __restrict__ lv,
            float* __restrict__ out)
{
    const int tid  = threadIdx.x;
    const int warp = tid >> 5;
    const int lane = tid & 31;
    const int bid  = blockIdx.x;

    const float* atts[4] = { xAr, xBr, xCr, comple };
    const float* labs[4] = { xA,  xB,  xC,  lab_enc };

    const uint32_t smem_base  = smem_u32(smem);
    const uint32_t full_base  = smem_base + NBUF * STAGE_BYTES;
    const uint32_t empty_base = full_base + NBUF * 8;

    if (tid == 0) {
#pragma unroll
        for (int k = 0; k < NBUF; k++) {
            asm volatile("mbarrier.init.shared.b64 [%0], 1;"  :: "r"(full_base  + k * 8) : "memory");
            asm volatile("mbarrier.init.shared.b64 [%0], %1;" :: "r"(empty_base + k * 8), "r"(NCONS) : "memory");
        }
        asm volatile("fence.proxy.async.shared::cta;" ::: "memory");
    }
    __syncthreads();

    const int nIter = (NSTAGE - bid + GRID - 1) / GRID;   // 27 or 28, >= NBUF

    float tube = 0.f, ce = 0.f, kl = 0.f;

    if (warp == NCONS) {
        // ---------------- producer warp ----------------
        if (lane == 0) {
            // prologue: fill all NBUF buffers
#pragma unroll
            for (int k = 0; k < NBUF; k++)
                issue_stage(bid + k * GRID, smem_base + k * STAGE_BYTES, full_base + k * 8,
                            atts, labs, mu, lv, fusion, labels);
            // steady state: wait for buffer to drain, refill immediately
            for (int nx = NBUF; nx < nIter; nx++) {
                const int buf = nx % NBUF;
                const uint32_t parity = ((nx / NBUF) - 1) & 1;
                mbar_wait(empty_base + buf * 8, parity);
                asm volatile("fence.proxy.async.shared::cta;" ::: "memory");
                issue_stage(bid + nx * GRID, smem_base + buf * STAGE_BYTES, full_base + buf * 8,
                            atts, labs, mu, lv, fusion, labels);
            }
        }
    } else {
        // ---------------- consumer warps (0..11), free-running ----------------
        int buf = 0;
        unsigned parity = 0;
        for (int it = 0; it < nIter; it++) {
            mbar_wait(full_base + buf * 8, parity);
            const float* bufp = smem + buf * STAGE_FLOATS;

            // 24 tasks over 12 warps: 0-15 tube (row=t>>2, pair=t&3), 16-19 KL, 20-23 CE
#pragma unroll
            for (int tt = 0; tt < 2; tt++) {
                const int t = warp * 2 + tt;
                if (t < 16) {
                    const int row = t >> 2, pair = t & 3;
                    const float4* a4 = (const float4*)(bufp + OFF_TUBE(pair, 0) + row * D);
                    const float4* g4 = (const float4*)(bufp + OFF_TUBE(pair, 1) + row * D);
                    float dot = 0.f, pp = 0.f, gg = 0.f;
#pragma unroll
                    for (int i = 0; i < 4; i++) {
                        float4 a = a4[lane + 32 * i];
                        float4 g = g4[lane + 32 * i];
                        dot += a.x * g.x + a.y * g.y + a.z * g.z + a.w * g.w;
                        pp  += a.x * a.x + a.y * a.y + a.z * a.z + a.w * a.w;
                        gg  += g.x * g.x + g.y * g.y + g.z * g.z + g.w * g.w;
                    }
                    dot = warp_sum(dot);
                    pp  = warp_sum(pp);
                    gg  = warp_sum(gg);
                    tube += tube_scalar(dot, pp, gg);
                } else if (t < 20) {
                    const int row = t - 16;
                    float4 m = ((const float4*)(bufp + OFF_MU + row * Z))[lane];
                    float4 l = ((const float4*)(bufp + OFF_LV + row * Z))[lane];
                    float k = (1.f + l.x - m.x * m.x - __expf(l.x))
                            + (1.f + l.y - m.y * m.y - __expf(l.y))
                            + (1.f + l.z - m.z * m.z - __expf(l.z))
                            + (1.f + l.w - m.w * m.w - __expf(l.w));
                    kl += warp_sum(k);
                } else {
                    const int row = t - 20;
                    const float* f  = bufp + OFF_F  + row * C;
                    const float* lb = bufp + OFF_LB + row * C;
                    float fmax = -INFINITY, lmax = -INFINITY;
                    int lidx = 0x7fffffff;
#pragma unroll
                    for (int q = 0; q < 4; q++) {
                        int i = lane + 32 * q;
                        if (i < C) {
                            float fv  = f[i];
                            float lvv = lb[i];
                            fmax = fmaxf(fmax, fv);
                            if (lvv > lmax || (lvv == lmax && i < lidx)) { lmax = lvv; lidx = i; }
                        }
                    }
#pragma unroll
                    for (int o = 16; o; o >>= 1) {
                        fmax = fmaxf(fmax, __shfl_xor_sync(0xffffffffu, fmax, o));
                        float ol = __shfl_xor_sync(0xffffffffu, lmax, o);
                        int   oi = __shfl_xor_sync(0xffffffffu, lidx, o);
                        if (ol > lmax || (ol == lmax && oi < lidx)) { lmax = ol; lidx = oi; }
                    }
                    float se = 0.f;
#pragma unroll
                    for (int q = 0; q < 4; q++) {
                        int i = lane + 32 * q;
                        if (i < C) se += __expf(f[i] - fmax);
                    }
                    se = warp_sum(se);
                    ce += -(f[lidx] - fmax - __logf(se));
                }
            }

            __syncwarp();
            if (lane == 0) mbar_arrive(empty_base + buf * 8);   // free this buffer

            if (++buf == NBUF) { buf = 0; parity ^= 1u; }
        }
    }

    // ---- block reduce + last-block finalize ----
    __shared__ float sT[13], sC[13], sK[13];
    if (lane == 0) { sT[warp] = tube; sC[warp] = ce; sK[warp] = kl; }
    __syncthreads();
    if (tid == 0) {
        float t = 0.f, c = 0.f, k = 0.f;
#pragma unroll
        for (int i = 0; i < NCONS; i++) { t += sT[i]; c += sC[i]; k += sK[i]; }
        atomicAdd(&g_acc[0], (double)t);
        atomicAdd(&g_acc[1], (double)c);
        atomicAdd(&g_acc[2], (double)k);
        __threadfence();
        unsigned prev = atomicAdd(&g_count, 1u);
        if (prev == gridDim.x - 1) {
            __threadfence();
            double tubeS = g_acc[0] / (double)B;                         // ALPHA = 1
            double ceS   = g_acc[1] / (double)B;
            double klS   = -0.5 * BETA * (g_acc[2] / ((double)B * (double)Z));
            out[0] = (float)(tubeS + ceS + klS);
            g_acc[0] = 0.0; g_acc[1] = 0.0; g_acc[2] = 0.0;
            g_count = 0u;
            __threadfence();
        }
    }
}

extern "C" void kernel_launch(void* const* d_in, const int* in_sizes, int n_in,
                              void* d_out, int out_size) {
    const float* fusion  = (const float*)d_in[0];
    const float* comple  = (const float*)d_in[1];
    const float* labels  = (const float*)d_in[2];
    const float* lab_enc = (const float*)d_in[3];
    const float* xA      = (const float*)d_in[4];
    const float* xAr     = (const float*)d_in[5];
    const float* xB      = (const float*)d_in[6];
    const float* xBr     = (const float*)d_in[7];
    const float* xC      = (const float*)d_in[8];
    const float* xCr     = (const float*)d_in[9];
    const float* mu      = (const float*)d_in[10];
    const float* lv      = (const float*)d_in[11];
    float* out = (float*)d_out;

    static int configured = 0;
    if (!configured) {
        cudaFuncSetAttribute(loss_kernel, cudaFuncAttributeMaxDynamicSharedMemorySize, SMEM_BYTES);
        configured = 1;
    }
    loss_kernel<<<GRID, THREADS, SMEM_BYTES>>>(fusion, comple, labels, lab_enc,
                                               xA, xAr, xB, xBr, xC, xCr, mu, lv, out);
}